// round 2
// baseline (speedup 1.0000x reference)
#include <cuda_runtime.h>
#include <math.h>

#define LL 4
#define BB 8
#define NS 1200
#define NL 128
#define CC 768
#define HH 448
#define WW 448
#define GS 56            // 448/8
#define GL 16            // ceil-stride 28 -> 16
#define MS (GS*GS)       // 3136
#define ML (GL*GL)       // 256

// Scratch (no allocation allowed)
__device__ float         g_d_s[LL*BB*NS];
__device__ unsigned char g_nz_s[LL*BB*NS];
__device__ float         g_d_l[LL*BB*NL];
__device__ unsigned char g_nz_l[LL*BB*NL];
__device__ unsigned char g_valid_s[BB*MS];
__device__ unsigned char g_valid_l[BB*ML];
__device__ float         g_loss[2*LL*BB];
__device__ int           g_act[2*LL*BB];

// ---------------------------------------------------------------------------
// Kernel 1: valid masks from f_k (channel dim is 1, so sum==pixel)
__global__ void valid_kernel(const float* __restrict__ fk) {
    int t = blockIdx.x * blockDim.x + threadIdx.x;
    if (t < BB*MS) {
        int b = t / MS, i = t % MS;
        int gy = i / GS, gx = i % GS;
        float v = fk[(size_t)b*HH*WW + (size_t)gy*8*WW + gx*8];
        g_valid_s[t] = (v > 0.f) ? 1 : 0;
    }
    int t2 = t - BB*MS;
    if (t2 >= 0 && t2 < BB*ML) {
        int b = t2 / ML, i = t2 % ML;
        int gy = i / GL, gx = i % GL;
        float v = fk[(size_t)b*HH*WW + (size_t)gy*28*WW + gx*28];
        g_valid_l[t2] = (v > 0.f) ? 1 : 0;
    }
}

// ---------------------------------------------------------------------------
// Kernel 2: per-row distance + nonzero flag. One warp per (l,b,n) row of 768.
// 6 independent float4 loads per lane -> high MLP, fully coalesced.
template<int N, bool IS_S>
__global__ void __launch_bounds__(256) dist_kernel(const float* __restrict__ sel,
                                                   const float* __restrict__ ker) {
    int warp = (blockIdx.x * blockDim.x + threadIdx.x) >> 5;
    int lane = threadIdx.x & 31;
    if (warp >= LL*BB*N) return;
    int lb = warp / N;

    const float4* s4 = reinterpret_cast<const float4*>(sel) + (size_t)warp * (CC/4);
    const float4* k4 = reinterpret_cast<const float4*>(ker) + (size_t)lb   * (CC/4);

    float acc = 0.f;
    unsigned orb = 0u;
    #pragma unroll
    for (int i = 0; i < CC/128; i++) {       // 6 iterations
        float4 sv = s4[lane + 32*i];
        float4 kv = k4[lane + 32*i];
        float d0 = kv.x - sv.x, d1 = kv.y - sv.y, d2 = kv.z - sv.z, d3 = kv.w - sv.w;
        acc = fmaf(d0, d0, acc); acc = fmaf(d1, d1, acc);
        acc = fmaf(d2, d2, acc); acc = fmaf(d3, d3, acc);
        orb |= __float_as_uint(sv.x) | __float_as_uint(sv.y)
             | __float_as_uint(sv.z) | __float_as_uint(sv.w);
    }
    #pragma unroll
    for (int o = 16; o; o >>= 1) {
        acc += __shfl_xor_sync(0xffffffffu, acc, o);
        orb |= __shfl_xor_sync(0xffffffffu, orb, o);
    }
    if (lane == 0) {
        if (IS_S) { g_d_s[warp] = sqrtf(acc); g_nz_s[warp] = ((orb & 0x7fffffffu) != 0u); }
        else      { g_d_l[warp] = sqrtf(acc); g_nz_l[warp] = ((orb & 0x7fffffffu) != 0u); }
    }
}

// ---------------------------------------------------------------------------
// Kernel 3: per-(l,b) masked means + softplus. Blocks 0..31 = scale s, 32..63 = scale l.
__global__ void __launch_bounds__(256) stats_kernel(const int* __restrict__ idx_s,
                                                    const int* __restrict__ idx_l) {
    bool is_s = blockIdx.x < LL*BB;
    int lb = is_s ? blockIdx.x : (blockIdx.x - LL*BB);
    int l = lb / BB, b = lb % BB;
    int N = is_s ? NS : NL;
    int M = is_s ? MS : ML;
    const float*         dA  = is_s ? g_d_s : g_d_l;
    const unsigned char* nzA = is_s ? g_nz_s : g_nz_l;
    const unsigned char* vA  = is_s ? g_valid_s : g_valid_l;
    const int*           iA  = is_s ? idx_s : idx_l;

    float sp = 0.f, sn = 0.f;
    int cp = 0, cn = 0;
    for (int n = (int)threadIdx.x; n < N; n += blockDim.x) {
        bool cv = false;
        #pragma unroll
        for (int bb = 0; bb < BB; bb++) cv = cv || (nzA[(l*BB + bb)*N + n] != 0);
        if (cv) {
            float d = dA[lb*N + n];
            bool member = vA[b*M + iA[lb*N + n]] != 0;
            if (member) { sp += d; cp++; } else { sn += d; cn++; }
        }
    }
    // warp reduce
    #pragma unroll
    for (int o = 16; o; o >>= 1) {
        sp += __shfl_xor_sync(0xffffffffu, sp, o);
        sn += __shfl_xor_sync(0xffffffffu, sn, o);
        cp += __shfl_xor_sync(0xffffffffu, cp, o);
        cn += __shfl_xor_sync(0xffffffffu, cn, o);
    }
    __shared__ float s_sp[8], s_sn[8];
    __shared__ int   s_cp[8], s_cn[8];
    int wid = threadIdx.x >> 5, ln = threadIdx.x & 31;
    if (ln == 0) { s_sp[wid] = sp; s_sn[wid] = sn; s_cp[wid] = cp; s_cn[wid] = cn; }
    __syncthreads();
    if (threadIdx.x == 0) {
        for (int w = 1; w < 8; w++) {
            s_sp[0] += s_sp[w]; s_sn[0] += s_sn[w];
            s_cp[0] += s_cp[w]; s_cn[0] += s_cn[w];
        }
        float ap = s_sp[0] / (float)max(s_cp[0], 1);
        float an = s_sn[0] / (float)max(s_cn[0], 1);
        float x = ap - an;
        // stable softplus == jax.nn.softplus
        float loss = fmaxf(x, 0.f) + log1pf(expf(-fabsf(x)));
        g_loss[blockIdx.x] = loss;
        g_act[blockIdx.x]  = (s_cp[0] > 0 && s_cn[0] > 0) ? 1 : 0;
    }
}

// ---------------------------------------------------------------------------
// Kernel 4: final scalar. 32 lanes, lane i handles (s[i], l[i]).
__global__ void final_kernel(float* __restrict__ out) {
    int i = threadIdx.x;  // 0..31
    int   as = g_act[i];
    float ls = g_loss[i];
    int   al = g_act[LL*BB + i] & as;   // act_l &= act_s
    float llv = g_loss[LL*BB + i];
    float tot = (as ? ls : 0.f) + (al ? llv : 0.f);
    int times = as + al;
    #pragma unroll
    for (int o = 16; o; o >>= 1) {
        tot   += __shfl_xor_sync(0xffffffffu, tot, o);
        times += __shfl_xor_sync(0xffffffffu, times, o);
    }
    if (i == 0) out[0] = (times > 0) ? tot / (float)times : 0.f;
}

// ---------------------------------------------------------------------------
extern "C" void kernel_launch(void* const* d_in, const int* in_sizes, int n_in,
                              void* d_out, int out_size) {
    const float* sel_s = (const float*)d_in[0];
    const int*   idx_s = (const int*)  d_in[1];
    const float* sel_l = (const float*)d_in[2];
    const int*   idx_l = (const int*)  d_in[3];
    const float* ker_s = (const float*)d_in[4];
    const float* ker_l = (const float*)d_in[5];
    const float* fk    = (const float*)d_in[6];

    valid_kernel<<<(BB*MS + BB*ML + 255)/256, 256>>>(fk);
    dist_kernel<NS, true ><<<(LL*BB*NS + 7)/8, 256>>>(sel_s, ker_s);
    dist_kernel<NL, false><<<(LL*BB*NL + 7)/8, 256>>>(sel_l, ker_l);
    stats_kernel<<<2*LL*BB, 256>>>(idx_s, idx_l);
    final_kernel<<<1, 32>>>((float*)d_out);
}

// round 3
// speedup vs baseline: 1.4472x; 1.4472x over previous
#include <cuda_runtime.h>
#include <math.h>

#define LL 4
#define BB 8
#define NS 1200
#define NL 128
#define CC 768
#define HH 448
#define WW 448
#define GS 56            // 448/8
#define GL 16            // 448/28
#define NWARP_S (LL*BB*NS)   // 38400
#define NWARP_L (LL*BB*NL)   // 4096
#define CHUNK_S 240          // 1200 = 5 * 240
#define NCHUNK_S 5
#define NBLK_STATS (LL*BB*NCHUNK_S + LL*BB)   // 160 + 32 = 192

// Scratch (no allocation allowed)
__device__ float         g_d_s[NWARP_S];
__device__ float         g_d_l[NWARP_L];
__device__ unsigned char g_nzT_s[LL*NS*BB];   // [l][n][b] -> 8B aligned per (l,n)
__device__ unsigned char g_nzT_l[LL*NL*BB];
__device__ float g_sp[NBLK_STATS], g_sn[NBLK_STATS];
__device__ int   g_cp[NBLK_STATS], g_cn[NBLK_STATS];

// ---------------------------------------------------------------------------
// Kernel 1: fused per-row distance + nonzero flag for BOTH scales.
// One warp per (l,b,n) row of 768 floats; 6 independent float4 loads/lane.
__global__ void __launch_bounds__(256) dist_fused(const float* __restrict__ sel_s,
                                                  const float* __restrict__ ker_s,
                                                  const float* __restrict__ sel_l,
                                                  const float* __restrict__ ker_l) {
    int w    = blockIdx.x * 8 + (threadIdx.x >> 5);
    int lane = threadIdx.x & 31;

    const float* sel; const float* ker;
    float* dOut; unsigned char* nzT;
    int N, row;
    if (w < NWARP_S) {
        row = w; N = NS; sel = sel_s; ker = ker_s; dOut = g_d_s; nzT = g_nzT_s;
    } else {
        row = w - NWARP_S;
        if (row >= NWARP_L) return;
        N = NL; sel = sel_l; ker = ker_l; dOut = g_d_l; nzT = g_nzT_l;
    }
    int lb = row / N, n = row % N;
    int l = lb / BB, b = lb % BB;

    const float4* s4 = reinterpret_cast<const float4*>(sel) + (size_t)row * (CC/4);
    const float4* k4 = reinterpret_cast<const float4*>(ker) + (size_t)lb  * (CC/4);

    float acc = 0.f;
    unsigned orb = 0u;
    #pragma unroll
    for (int i = 0; i < CC/128; i++) {       // 6 iterations, all independent
        float4 sv = s4[lane + 32*i];
        float4 kv = k4[lane + 32*i];
        float d0 = kv.x - sv.x, d1 = kv.y - sv.y, d2 = kv.z - sv.z, d3 = kv.w - sv.w;
        acc = fmaf(d0, d0, acc); acc = fmaf(d1, d1, acc);
        acc = fmaf(d2, d2, acc); acc = fmaf(d3, d3, acc);
        orb |= __float_as_uint(sv.x) | __float_as_uint(sv.y)
             | __float_as_uint(sv.z) | __float_as_uint(sv.w);
    }
    #pragma unroll
    for (int o = 16; o; o >>= 1) {
        acc += __shfl_xor_sync(0xffffffffu, acc, o);
        orb |= __shfl_xor_sync(0xffffffffu, orb, o);
    }
    if (lane == 0) {
        dOut[row] = sqrtf(acc);
        nzT[(size_t)(l*N + n)*BB + b] = ((orb & 0x7fffffffu) != 0u) ? 1 : 0;
    }
}

// ---------------------------------------------------------------------------
// Kernel 2: partial masked sums. Blocks [0,160): scale s (5 chunks of 240 per
// (l,b)); blocks [160,192): scale l (one chunk of 128 per (l,b)).
// col_valid = one 8-byte load; membership = direct f_k gather (no valid table).
__global__ void __launch_bounds__(256) stats_partial(const int* __restrict__ idx_s,
                                                     const int* __restrict__ idx_l,
                                                     const float* __restrict__ fk) {
    int blk = blockIdx.x;
    bool is_s = blk < LL*BB*NCHUNK_S;
    int g, n0, nCnt, N;
    if (is_s) { g = blk / NCHUNK_S; n0 = (blk % NCHUNK_S) * CHUNK_S; nCnt = CHUNK_S; N = NS; }
    else      { g = blk - LL*BB*NCHUNK_S; n0 = 0; nCnt = NL; N = NL; }
    int l = g / BB, b = g % BB;

    float sp = 0.f, sn = 0.f;
    int cp = 0, cn = 0;
    int t = (int)threadIdx.x;
    if (t < nCnt) {
        int n = n0 + t;
        unsigned long long nz64;
        float d; int idx; bool member;
        if (is_s) {
            nz64 = *reinterpret_cast<const unsigned long long*>(g_nzT_s + (size_t)(l*NS + n)*8);
            d    = g_d_s[g*NS + n];
            idx  = idx_s[g*NS + n];
            int gy = idx / GS, gx = idx % GS;
            member = fk[(size_t)b*HH*WW + (size_t)gy*8*WW + gx*8] > 0.f;
        } else {
            nz64 = *reinterpret_cast<const unsigned long long*>(g_nzT_l + (size_t)(l*NL + n)*8);
            d    = g_d_l[g*NL + n];
            idx  = idx_l[g*NL + n];
            int gy = idx / GL, gx = idx % GL;
            member = fk[(size_t)b*HH*WW + (size_t)gy*28*WW + gx*28] > 0.f;
        }
        if (nz64 != 0ull) {
            if (member) { sp = d; cp = 1; } else { sn = d; cn = 1; }
        }
    }
    // block reduce (8 warps)
    #pragma unroll
    for (int o = 16; o; o >>= 1) {
        sp += __shfl_xor_sync(0xffffffffu, sp, o);
        sn += __shfl_xor_sync(0xffffffffu, sn, o);
        cp += __shfl_xor_sync(0xffffffffu, cp, o);
        cn += __shfl_xor_sync(0xffffffffu, cn, o);
    }
    __shared__ float s_sp[8], s_sn[8];
    __shared__ int   s_cp[8], s_cn[8];
    int wid = t >> 5, ln = t & 31;
    if (ln == 0) { s_sp[wid] = sp; s_sn[wid] = sn; s_cp[wid] = cp; s_cn[wid] = cn; }
    __syncthreads();
    if (t == 0) {
        float tsp = 0.f, tsn = 0.f; int tcp = 0, tcn = 0;
        #pragma unroll
        for (int wI = 0; wI < 8; wI++) { tsp += s_sp[wI]; tsn += s_sn[wI]; tcp += s_cp[wI]; tcn += s_cn[wI]; }
        g_sp[blk] = tsp; g_sn[blk] = tsn; g_cp[blk] = tcp; g_cn[blk] = tcn;
    }
}

// ---------------------------------------------------------------------------
// Kernel 3: finish. 64 threads: t<32 -> s-group t (sum 5 chunk slots),
// t>=32 -> l-group t-32 (one slot). Then combine pairs, reduce, write scalar.
__global__ void final_kernel(float* __restrict__ out) {
    int t = (int)threadIdx.x;   // 0..63
    float sp = 0.f, sn = 0.f; int cp = 0, cn = 0;
    if (t < 32) {
        #pragma unroll
        for (int c = 0; c < NCHUNK_S; c++) {
            int s = t*NCHUNK_S + c;
            sp += g_sp[s]; sn += g_sn[s]; cp += g_cp[s]; cn += g_cn[s];
        }
    } else {
        int s = LL*BB*NCHUNK_S + (t - 32);
        sp = g_sp[s]; sn = g_sn[s]; cp = g_cp[s]; cn = g_cn[s];
    }
    float ap = sp / (float)max(cp, 1);
    float an = sn / (float)max(cn, 1);
    float x = ap - an;
    float loss = fmaxf(x, 0.f) + log1pf(expf(-fabsf(x)));   // stable softplus
    int act = (cp > 0 && cn > 0) ? 1 : 0;

    __shared__ float s_loss[64];
    __shared__ int   s_act[64];
    s_loss[t] = loss; s_act[t] = act;
    __syncthreads();
    if (t < 32) {
        int   as  = s_act[t];
        int   al  = s_act[32 + t] & as;        // act_l &= act_s
        float tot = (as ? s_loss[t] : 0.f) + (al ? s_loss[32 + t] : 0.f);
        int times = as + al;
        #pragma unroll
        for (int o = 16; o; o >>= 1) {
            tot   += __shfl_xor_sync(0xffffffffu, tot, o);
            times += __shfl_xor_sync(0xffffffffu, times, o);
        }
        if (t == 0) out[0] = (times > 0) ? tot / (float)times : 0.f;
    }
}

// ---------------------------------------------------------------------------
extern "C" void kernel_launch(void* const* d_in, const int* in_sizes, int n_in,
                              void* d_out, int out_size) {
    const float* sel_s = (const float*)d_in[0];
    const int*   idx_s = (const int*)  d_in[1];
    const float* sel_l = (const float*)d_in[2];
    const int*   idx_l = (const int*)  d_in[3];
    const float* ker_s = (const float*)d_in[4];
    const float* ker_l = (const float*)d_in[5];
    const float* fk    = (const float*)d_in[6];

    int nblk = (NWARP_S + NWARP_L + 7) / 8;   // 8 warps per 256-thread block
    dist_fused<<<nblk, 256>>>(sel_s, ker_s, sel_l, ker_l);
    stats_partial<<<NBLK_STATS, 256>>>(idx_s, idx_l, fk);
    final_kernel<<<1, 64>>>((float*)d_out);
}